// round 16
// baseline (speedup 1.0000x reference)
#include <cuda_runtime.h>
#include <cuda_bf16.h>
#include <cstdint>

#define DT2 1.0e-6f

// ---------------- device scratch (no allocations allowed) ----------------
static constexpr int KSPLIT = 16;
__device__ float g_partial[KSPLIT * 4096 * 64];  // [ksplit][row*64+s]
__device__ float g_acc[4096 * 64];               // reduced (overwritten each launch)

static __device__ __forceinline__ uint32_t smem_u32(const void* p) {
    uint32_t a;
    asm("{ .reg .u64 t; cvta.to.shared.u64 t, %1; cvt.u32.u64 %0, t; }"
        : "=r"(a) : "l"(p));
    return a;
}

// ===================== kernel 1: tf32 mma.sync GEMM, 5-stage cp.async, 3 CTAs/SM =====================
// P[ksplit][row0:+128][0:64] = deno[row0:+128, k0:+256] @ X[k0:+256, 0:64]
// grid (32, 16) = 512 CTAs; 3 CTAs/SM (444 slots) -> 24 warps/SM.
// 256 threads = 8 warps, warp grid 4(M) x 2(N), warp tile 32x32.
// Kc = 16 fp32 per chunk (16 chunks), 5-stage cp.async pipeline, raw fp32 -> tf32 mma.
//
// SMEM per stage: A [128 rows][16 fp32], row stride 80B (20 words; banks 20g+tig all distinct)
//                 B [16 k][64 fp32],     row stride 288B (72 words; verified conflict-free)
static constexpr uint32_t A_ST   = 80;
static constexpr uint32_t ABYTES = 128 * A_ST;            // 10240
static constexpr uint32_t B_ST   = 288;
static constexpr uint32_t BBYTES = 16 * B_ST;             // 4608
static constexpr uint32_t STAGE_SZ = ABYTES + BBYTES;     // 14848
static constexpr int STAGES = 5;
static constexpr uint32_t SMEM_REQ = STAGES * STAGE_SZ;   // 74240

static constexpr int KPER = 4096 / KSPLIT;                // 256
static constexpr int KC = 16;
static constexpr int NCHUNK = KPER / KC;                  // 16

#define CP_ASYNC16(saddr, gptr) \
    asm volatile("cp.async.cg.shared.global [%0], [%1], 16;" \
                 :: "r"(saddr), "l"(gptr) : "memory")
#define CP_COMMIT() asm volatile("cp.async.commit_group;" ::: "memory")
#define CP_WAIT(N)  asm volatile("cp.async.wait_group %0;" :: "n"(N) : "memory")

static __device__ __forceinline__ void mma_tf32(
    float* c, uint32_t a0, uint32_t a1, uint32_t a2, uint32_t a3,
    uint32_t b0, uint32_t b1)
{
    asm volatile(
        "mma.sync.aligned.m16n8k8.row.col.f32.tf32.tf32.f32 "
        "{%0,%1,%2,%3}, {%4,%5,%6,%7}, {%8,%9}, {%0,%1,%2,%3};"
        : "+f"(c[0]), "+f"(c[1]), "+f"(c[2]), "+f"(c[3])
        : "r"(a0), "r"(a1), "r"(a2), "r"(a3), "r"(b0), "r"(b1));
}

__global__ __launch_bounds__(256, 3) void ws_gemm_kernel(
    const float* __restrict__ deno, const float* __restrict__ X)
{
    extern __shared__ char sm[];
    const uint32_t smb = smem_u32(sm);

    const int tid = threadIdx.x;
    const int wid = tid >> 5;
    const int lid = tid & 31;
    const int wm = wid >> 1;          // 0..3 : warp M index
    const int wn = wid & 1;           // 0..1 : warp N index
    const int g = lid >> 2;           // group 0..7
    const int tig = lid & 3;          // thread-in-group

    const int row0 = blockIdx.x * 128;
    const int k0 = blockIdx.y * KPER;

    float acc[2][4][4];
#pragma unroll
    for (int i = 0; i < 2; i++)
#pragma unroll
        for (int j = 0; j < 4; j++)
#pragma unroll
            for (int q = 0; q < 4; q++) acc[i][j][q] = 0.0f;

    // issue one chunk's cp.async into stage buffer s (3 x 16B per thread)
    auto issue_stage = [&](int s, int kc) {
        uint32_t Ab = smb + (uint32_t)s * STAGE_SZ;
        uint32_t Bb = Ab + ABYTES;
        // A: 128 rows x 4 x 16B = 512 ops, 2 per thread
#pragma unroll
        for (int i = 0; i < 2; i++) {
            int o = i * 256 + tid;
            int r = o >> 2, seg = o & 3;
            CP_ASYNC16(Ab + (uint32_t)r * A_ST + (uint32_t)seg * 16,
                       deno + (size_t)(row0 + r) * 4096 + kc + seg * 4);
        }
        // B: 16 rows x 16 x 16B = 256 ops, 1 per thread
        {
            int r = tid >> 4, seg = tid & 15;
            CP_ASYNC16(Bb + (uint32_t)r * B_ST + (uint32_t)seg * 16,
                       X + (size_t)(kc + r) * 64 + seg * 4);
        }
    };

    // ---- prologue: issue stages 0..3 ----
    issue_stage(0, k0);          CP_COMMIT();
    issue_stage(1, k0 + KC);     CP_COMMIT();
    issue_stage(2, k0 + 2 * KC); CP_COMMIT();
    issue_stage(3, k0 + 3 * KC); CP_COMMIT();

    // fragment base offsets within a stage (bytes)
    const uint32_t a_base = (uint32_t)(wm * 32 + g) * A_ST + (uint32_t)tig * 4;
    const uint32_t b_base = ABYTES + (uint32_t)tig * B_ST + (uint32_t)(wn * 32 + g) * 4;

#pragma unroll 1
    for (int c = 0; c < NCHUNK; c++) {
        // wait for stage c (outstanding groups after wait: min(3, NCHUNK-1-c))
        if (c <= NCHUNK - 4)      { CP_WAIT(3); }
        else if (c == NCHUNK - 3) { CP_WAIT(2); }
        else if (c == NCHUNK - 2) { CP_WAIT(1); }
        else                      { CP_WAIT(0); }
        __syncthreads();   // all warps done with stage (c+4)%5's previous contents

        if (c + 4 < NCHUNK) {
            issue_stage((c + 4) % STAGES, k0 + (c + 4) * KC);
            CP_COMMIT();
        }

        const char* St = sm + (size_t)(c % STAGES) * STAGE_SZ;
#pragma unroll
        for (int ks = 0; ks < 2; ks++) {
            uint32_t a[2][4];
#pragma unroll
            for (int mf = 0; mf < 2; mf++) {
                const char* ap = St + a_base + (uint32_t)mf * (16 * A_ST) + (uint32_t)ks * 32;
                a[mf][0] = *reinterpret_cast<const uint32_t*>(ap);
                a[mf][1] = *reinterpret_cast<const uint32_t*>(ap + 8 * A_ST);
                a[mf][2] = *reinterpret_cast<const uint32_t*>(ap + 16);
                a[mf][3] = *reinterpret_cast<const uint32_t*>(ap + 8 * A_ST + 16);
            }
#pragma unroll
            for (int nf = 0; nf < 4; nf++) {
                const char* bp = St + b_base + (uint32_t)ks * (8 * B_ST) + (uint32_t)nf * 32;
                uint32_t b0 = *reinterpret_cast<const uint32_t*>(bp);
                uint32_t b1 = *reinterpret_cast<const uint32_t*>(bp + 4 * B_ST);
                mma_tf32(acc[0][nf], a[0][0], a[0][1], a[0][2], a[0][3], b0, b1);
                mma_tf32(acc[1][nf], a[1][0], a[1][1], a[1][2], a[1][3], b0, b1);
            }
        }
    }

    // ---- epilogue: plain coalesced STG of partials (no atomics) ----
    float* Pp = g_partial + (size_t)blockIdx.y * (4096 * 64);
#pragma unroll
    for (int mf = 0; mf < 2; mf++) {
#pragma unroll
        for (int nf = 0; nf < 4; nf++) {
            int row = row0 + wm * 32 + mf * 16 + g;
            int col = wn * 32 + nf * 8 + tig * 2;
            float2 v0 = make_float2(acc[mf][nf][0], acc[mf][nf][1]);
            float2 v1 = make_float2(acc[mf][nf][2], acc[mf][nf][3]);
            *reinterpret_cast<float2*>(Pp + (size_t)row * 64 + col) = v0;
            *reinterpret_cast<float2*>(Pp + (size_t)(row + 8) * 64 + col) = v1;
        }
    }
}

// ===================== kernel 1b: reduce KSPLIT partials -> g_acc (overwrite) =====================
__global__ __launch_bounds__(256) void ws_reduce_kernel()
{
    int f4 = blockIdx.x * 256 + threadIdx.x;   // 0 .. 65535 float4 slots
    float4 t = *reinterpret_cast<const float4*>(g_partial + (size_t)f4 * 4);
#pragma unroll
    for (int p = 1; p < KSPLIT; p++) {
        float4 v = *reinterpret_cast<const float4*>(
            g_partial + (size_t)p * 262144 + (size_t)f4 * 4);
        t.x += v.x; t.y += v.y; t.z += v.z; t.w += v.w;
    }
    *reinterpret_cast<float4*>(g_acc + (size_t)f4 * 4) = t;
}

// ===================== kernel 2: fused out = Y + dt^2 * scatter(acc) =====================
__global__ __launch_bounds__(256) void ws_copy_kernel(
    const float* __restrict__ Y, const int* __restrict__ xidx,
    float* __restrict__ out)
{
    __shared__ int fast_s;
    __shared__ unsigned char inv_s[4096];

    const int tid = threadIdx.x;
    const size_t base = (size_t)blockIdx.x * 4096;   // float4 index of first elem

    if (tid == 0) fast_s = 1;
    __syncthreads();
    if (tid < 64) {
        if (__ldg(xidx + tid) != tid * 64) fast_s = 0;
    }
    __syncthreads();

    if (fast_s) {
        const bool adder = (tid & 15) == 0;
#pragma unroll
        for (int half = 0; half < 2; half++) {
            float4 v[8];
#pragma unroll
            for (int i = 0; i < 8; i++) {
                size_t idx = base + (half * 8 + i) * 256 + tid;
                v[i] = __ldcs(reinterpret_cast<const float4*>(Y) + idx);
            }
            if (adder) {
#pragma unroll
                for (int i = 0; i < 8; i++) {
                    size_t idx = base + (half * 8 + i) * 256 + tid;
                    int row = (int)(idx >> 10);
                    int s = (int)((idx & 1023) >> 4);
                    v[i].x += DT2 * g_acc[row * 64 + s];
                }
            }
#pragma unroll
            for (int i = 0; i < 8; i++) {
                size_t idx = base + (half * 8 + i) * 256 + tid;
                __stcs(reinterpret_cast<float4*>(out) + idx, v[i]);
            }
        }
    } else {
        // general fallback: per-element inverse-table lookup
        reinterpret_cast<int4*>(inv_s)[tid] = make_int4(0, 0, 0, 0);
        __syncthreads();
        if (tid < 64) inv_s[__ldg(xidx + tid)] = (unsigned char)(tid + 1);
        __syncthreads();
#pragma unroll
        for (int it = 0; it < 16; it++) {
            size_t idx = base + it * 256 + tid;
            int row = (int)(idx >> 10);
            int c4 = (int)(idx & 1023);
            float4 v = __ldcs(reinterpret_cast<const float4*>(Y) + idx);
            uchar4 u = *reinterpret_cast<const uchar4*>(&inv_s[c4 * 4]);
            if (u.x | u.y | u.z | u.w) {
                int rb = row * 64;
                if (u.x) v.x += DT2 * g_acc[rb + u.x - 1];
                if (u.y) v.y += DT2 * g_acc[rb + u.y - 1];
                if (u.z) v.z += DT2 * g_acc[rb + u.z - 1];
                if (u.w) v.w += DT2 * g_acc[rb + u.w - 1];
            }
            __stcs(reinterpret_cast<float4*>(out) + idx, v);
        }
    }
}

// ===================== launch =====================
extern "C" void kernel_launch(void* const* d_in, const int* in_sizes, int n_in,
                              void* d_out, int out_size)
{
    const float* Y    = (const float*)d_in[0];
    const float* X    = (const float*)d_in[1];
    const float* deno = (const float*)d_in[2];
    const int*   xi   = (const int*)d_in[3];
    float* out = (float*)d_out;

    cudaFuncSetAttribute(ws_gemm_kernel,
                         cudaFuncAttributeMaxDynamicSharedMemorySize, SMEM_REQ);

    ws_gemm_kernel<<<dim3(32, KSPLIT), 256, SMEM_REQ>>>(deno, X);
    ws_reduce_kernel<<<256, 256>>>();
    ws_copy_kernel<<<1024, 256>>>(Y, xi, out);
}

// round 17
// speedup vs baseline: 1.1887x; 1.1887x over previous
#include <cuda_runtime.h>
#include <cuda_bf16.h>
#include <cstdint>

#define DT2 1.0e-6f

// ---------------- device scratch (no allocations allowed) ----------------
// Zero-initialized at load; ws_copy re-zeroes after each consume (replay-invariant).
__device__ float g_acc[4096 * 64];   // [row*64+s], atomic-accumulated by gemm

static __device__ __forceinline__ uint32_t smem_u32(const void* p) {
    uint32_t a;
    asm("{ .reg .u64 t; cvta.to.shared.u64 t, %1; cvt.u32.u64 %0, t; }"
        : "=r"(a) : "l"(p));
    return a;
}

// ===================== kernel 1: bf16 mma.sync GEMM, M-tile 64, 3 CTAs/SM =====================
// acc[row0:+64][0:64] += deno[row0:+64, k0:+512] @ X[k0:+512, 0:64]   (atomics)
// grid (64, 8) = 512 CTAs; __launch_bounds__(256,3) -> 24 warps/SM.
// 256 threads = 8 warps, warp grid 4(M) x 2(N), warp tile 16x32.
// Kc = 64 per chunk (8 chunks), double buffered, register prefetch (4+4 float4).
static constexpr uint32_t TSTRIDE = 144;                   // bytes per bf16 row (72 bf16)
static constexpr uint32_t ABUF = 64 * TSTRIDE;             // 9216
static constexpr uint32_t BBUF = 64 * TSTRIDE;             // 9216
static constexpr uint32_t SMEM_REQ = 2 * ABUF + 2 * BBUF;  // 36864

static constexpr int KSPLIT = 8;
static constexpr int KPER = 4096 / KSPLIT;                 // 512
static constexpr int NCHUNK = KPER / 64;                   // 8

static __device__ __forceinline__ void ldsm_x4(uint32_t* r, uint32_t addr)
{
    asm volatile(
        "ldmatrix.sync.aligned.m8n8.x4.shared.b16 {%0,%1,%2,%3}, [%4];"
        : "=r"(r[0]), "=r"(r[1]), "=r"(r[2]), "=r"(r[3]) : "r"(addr));
}

static __device__ __forceinline__ void ldsm_x4_trans(uint32_t* r, uint32_t addr)
{
    asm volatile(
        "ldmatrix.sync.aligned.m8n8.x4.trans.shared.b16 {%0,%1,%2,%3}, [%4];"
        : "=r"(r[0]), "=r"(r[1]), "=r"(r[2]), "=r"(r[3]) : "r"(addr));
}

static __device__ __forceinline__ void mma_bf16(
    float* c, const uint32_t* a, uint32_t b0, uint32_t b1)
{
    asm volatile(
        "mma.sync.aligned.m16n8k16.row.col.f32.bf16.bf16.f32 "
        "{%0,%1,%2,%3}, {%4,%5,%6,%7}, {%8,%9}, {%0,%1,%2,%3};"
        : "+f"(c[0]), "+f"(c[1]), "+f"(c[2]), "+f"(c[3])
        : "r"(a[0]), "r"(a[1]), "r"(a[2]), "r"(a[3]), "r"(b0), "r"(b1));
}

static __device__ __forceinline__ uint32_t f4_to_bf16x2_lo(float a, float b) {
    __nv_bfloat162 p = __float22bfloat162_rn(make_float2(a, b));
    return *reinterpret_cast<uint32_t*>(&p);
}

__global__ __launch_bounds__(256, 3) void ws_gemm_kernel(
    const float* __restrict__ deno, const float* __restrict__ X)
{
    extern __shared__ char sm[];
    const uint32_t smb = smem_u32(sm);

    const int tid = threadIdx.x;
    const int wid = tid >> 5;
    const int lid = tid & 31;
    const int wm = wid >> 1;          // 0..3 : warp M index (16 rows each)
    const int wn = wid & 1;           // 0..1 : warp N index (32 cols each)
    const int g = lid >> 2;           // group 0..7
    const int tig = lid & 3;          // thread-in-group

    const int row0 = blockIdx.x * 64;
    const int k0 = blockIdx.y * KPER;

    float acc[4][4];                  // [nf][reg] — warp tile 16x32, one m-frag
#pragma unroll
    for (int j = 0; j < 4; j++)
#pragma unroll
        for (int q = 0; q < 4; q++) acc[j][q] = 0.0f;

    // staging: A = 64 rows x 16 f4 = 1024 f4 (4/thread); B identical shape
    // ---- prologue: stage chunk 0 into buffer 0 ----
    {
        const int kc = k0;
#pragma unroll
        for (int it = 0; it < 4; it++) {
            int lin = it * 256 + tid;
            int r = lin >> 4, c4 = lin & 15;
            float4 v = *reinterpret_cast<const float4*>(
                deno + (size_t)(row0 + r) * 4096 + kc + c4 * 4);
            uint2 w;
            w.x = f4_to_bf16x2_lo(v.x, v.y);
            w.y = f4_to_bf16x2_lo(v.z, v.w);
            *reinterpret_cast<uint2*>(sm + r * TSTRIDE + c4 * 8) = w;
        }
#pragma unroll
        for (int it = 0; it < 4; it++) {
            int lin = it * 256 + tid;
            int k = lin >> 4, f4 = lin & 15;
            float4 v = *reinterpret_cast<const float4*>(
                X + (size_t)(kc + k) * 64 + f4 * 4);
            uint2 w;
            w.x = f4_to_bf16x2_lo(v.x, v.y);
            w.y = f4_to_bf16x2_lo(v.z, v.w);
            *reinterpret_cast<uint2*>(sm + 2 * ABUF + k * TSTRIDE + f4 * 8) = w;
        }
    }
    __syncthreads();

    // fragment base offsets (bytes within a buffer)
    // A (ldmatrix): row = wm*16 + (lid&7) + ((lid>>3)&1)*8, col-16B = (lid>>4)
    const uint32_t a_off0 = (uint32_t)(wm * 16 + (lid & 7) + ((lid >> 3) & 1) * 8) * TSTRIDE
                          + (uint32_t)(lid >> 4) * 16;
    // B (ldmatrix.trans): k = (lid&7) + ((lid>>3)&1)*8, n0 = wn*32 + (lid>>4)*8
    const uint32_t b_off0 = (uint32_t)((lid & 7) + ((lid >> 3) & 1) * 8) * TSTRIDE
                          + (uint32_t)(wn * 32 + (lid >> 4) * 8) * 2;

#pragma unroll 1
    for (int c = 0; c < NCHUNK; c++) {
        const int buf = c & 1;
        const uint32_t Ab = smb + buf * ABUF;
        const uint32_t Bb = smb + 2 * ABUF + buf * BBUF;

        // issue global loads for next chunk into registers (4 + 4 float4)
        float4 aR[4];
        float4 bR[4];
        if (c < NCHUNK - 1) {
            const int kc = k0 + (c + 1) * 64;
#pragma unroll
            for (int it = 0; it < 4; it++) {
                int lin = it * 256 + tid;
                int r = lin >> 4, c4 = lin & 15;
                aR[it] = *reinterpret_cast<const float4*>(
                    deno + (size_t)(row0 + r) * 4096 + kc + c4 * 4);
            }
#pragma unroll
            for (int it = 0; it < 4; it++) {
                int lin = it * 256 + tid;
                int k = lin >> 4, f4 = lin & 15;
                bR[it] = *reinterpret_cast<const float4*>(
                    X + (size_t)(kc + k) * 64 + f4 * 4);
            }
        }

        // compute chunk c: 4 k-steps of 16
#pragma unroll
        for (int ks = 0; ks < 4; ks++) {
            uint32_t af[4];
            ldsm_x4(af, Ab + a_off0 + ks * 32);
#pragma unroll
            for (int nf2 = 0; nf2 < 2; nf2++) {
                uint32_t br[4];
                ldsm_x4_trans(br, Bb + b_off0 + (uint32_t)(ks * 16) * TSTRIDE
                                   + (uint32_t)(nf2 * 16) * 2);
                mma_bf16(acc[nf2 * 2 + 0], af, br[0], br[1]);
                mma_bf16(acc[nf2 * 2 + 1], af, br[2], br[3]);
            }
        }

        // store next chunk into other buffer
        if (c < NCHUNK - 1) {
            const int nb = (c + 1) & 1;
            char* Abp = sm + nb * ABUF;
            char* Bbp = sm + 2 * ABUF + nb * BBUF;
#pragma unroll
            for (int it = 0; it < 4; it++) {
                int lin = it * 256 + tid;
                int r = lin >> 4, c4 = lin & 15;
                uint2 w;
                w.x = f4_to_bf16x2_lo(aR[it].x, aR[it].y);
                w.y = f4_to_bf16x2_lo(aR[it].z, aR[it].w);
                *reinterpret_cast<uint2*>(Abp + r * TSTRIDE + c4 * 8) = w;
            }
#pragma unroll
            for (int it = 0; it < 4; it++) {
                int lin = it * 256 + tid;
                int k = lin >> 4, f4 = lin & 15;
                uint2 w;
                w.x = f4_to_bf16x2_lo(bR[it].x, bR[it].y);
                w.y = f4_to_bf16x2_lo(bR[it].z, bR[it].w);
                *reinterpret_cast<uint2*>(Bbp + k * TSTRIDE + f4 * 8) = w;
            }
        }
        __syncthreads();
    }

    // ---- epilogue: coalesced atomic accumulate into g_acc (1MB, L2-resident) ----
#pragma unroll
    for (int nf = 0; nf < 4; nf++) {
        int row = row0 + wm * 16 + g;
        int col = wn * 32 + nf * 8 + tig * 2;
        float* p0 = g_acc + (size_t)row * 64 + col;
        float* p1 = g_acc + (size_t)(row + 8) * 64 + col;
        atomicAdd(p0,     acc[nf][0]);
        atomicAdd(p0 + 1, acc[nf][1]);
        atomicAdd(p1,     acc[nf][2]);
        atomicAdd(p1 + 1, acc[nf][3]);
    }
}

// ===================== kernel 2: fused out = Y + dt^2 * scatter(acc) =====================
// R10-measured kernel (19.3us): inline structure check; fast path adds only at
// lanes with tid%16==0; block zeroes its g_acc slice after consuming it.
__global__ __launch_bounds__(256) void ws_copy_kernel(
    const float* __restrict__ Y, const int* __restrict__ xidx,
    float* __restrict__ out)
{
    __shared__ int fast_s;
    __shared__ unsigned char inv_s[4096];

    const int tid = threadIdx.x;
    const size_t base = (size_t)blockIdx.x * 4096;   // float4 index of first elem

    if (tid == 0) fast_s = 1;
    __syncthreads();
    if (tid < 64) {
        if (__ldg(xidx + tid) != tid * 64) fast_s = 0;
    }
    __syncthreads();

    if (fast_s) {
        const bool adder = (tid & 15) == 0;
#pragma unroll
        for (int half = 0; half < 2; half++) {
            float4 v[8];
#pragma unroll
            for (int i = 0; i < 8; i++) {
                size_t idx = base + (half * 8 + i) * 256 + tid;
                v[i] = __ldcs(reinterpret_cast<const float4*>(Y) + idx);
            }
            if (adder) {
#pragma unroll
                for (int i = 0; i < 8; i++) {
                    size_t idx = base + (half * 8 + i) * 256 + tid;
                    int row = (int)(idx >> 10);
                    int s = (int)((idx & 1023) >> 4);
                    v[i].x += DT2 * g_acc[row * 64 + s];
                }
            }
#pragma unroll
            for (int i = 0; i < 8; i++) {
                size_t idx = base + (half * 8 + i) * 256 + tid;
                __stcs(reinterpret_cast<float4*>(out) + idx, v[i]);
            }
        }
    } else {
        // general fallback: per-element inverse-table lookup
        reinterpret_cast<int4*>(inv_s)[tid] = make_int4(0, 0, 0, 0);
        __syncthreads();
        if (tid < 64) inv_s[__ldg(xidx + tid)] = (unsigned char)(tid + 1);
        __syncthreads();
#pragma unroll
        for (int it = 0; it < 16; it++) {
            size_t idx = base + it * 256 + tid;
            int row = (int)(idx >> 10);
            int c4 = (int)(idx & 1023);
            float4 v = __ldcs(reinterpret_cast<const float4*>(Y) + idx);
            uchar4 u = *reinterpret_cast<const uchar4*>(&inv_s[c4 * 4]);
            if (u.x | u.y | u.z | u.w) {
                int rb = row * 64;
                if (u.x) v.x += DT2 * g_acc[rb + u.x - 1];
                if (u.y) v.y += DT2 * g_acc[rb + u.y - 1];
                if (u.z) v.z += DT2 * g_acc[rb + u.z - 1];
                if (u.w) v.w += DT2 * g_acc[rb + u.w - 1];
            }
            __stcs(reinterpret_cast<float4*>(out) + idx, v);
        }
    }

    // restore acc == 0 for the next launch/replay (this block's 4 rows)
    __syncthreads();
    g_acc[blockIdx.x * 256 + tid] = 0.0f;
}

// ===================== launch =====================
extern "C" void kernel_launch(void* const* d_in, const int* in_sizes, int n_in,
                              void* d_out, int out_size)
{
    const float* Y    = (const float*)d_in[0];
    const float* X    = (const float*)d_in[1];
    const float* deno = (const float*)d_in[2];
    const int*   xi   = (const int*)d_in[3];
    float* out = (float*)d_out;

    cudaFuncSetAttribute(ws_gemm_kernel,
                         cudaFuncAttributeMaxDynamicSharedMemorySize, SMEM_REQ);

    ws_gemm_kernel<<<dim3(64, KSPLIT), 256, SMEM_REQ>>>(deno, X);
    ws_copy_kernel<<<1024, 256>>>(Y, xi, out);
}